// round 9
// baseline (speedup 1.0000x reference)
#include <cuda_runtime.h>
#include <cstdint>

#define TT 2048
#define BB 128
#define HH 200
#define HP 224        // padded h length: 8 chunks x 28; slots 220,221=x, 222=1.0
#define KC 28         // k-span per chunk (7 x LDS.128)
#define JT 52         // j-quads (4 j each): 52*4 = 208 >= 200
// compute threads: tid = jt*8 + kc, kc in [0,8), jt in [0,52) -> 416 = 13 warps
// warp 13 (tid 416..447): output head (overlapped) + x staging

typedef unsigned long long ull;

__device__ __forceinline__ ull pack2(float lo, float hi) {
    ull r; asm("mov.b64 %0, {%1,%2};" : "=l"(r) : "f"(lo), "f"(hi)); return r;
}
__device__ __forceinline__ void fma2(ull& acc, ull a, ull b) {
    asm("fma.rn.f32x2 %0, %1, %2, %0;" : "+l"(acc) : "l"(a), "l"(b));
}
__device__ __forceinline__ void unpack2(ull v, float& lo, float& hi) {
    asm("mov.b64 {%0,%1}, %2;" : "=f"(lo), "=f"(hi) : "l"(v));
}
__device__ __forceinline__ float tanh_hw(float x) {
    float r; asm("tanh.approx.f32 %0, %1;" : "=f"(r) : "f"(x));
    return r;
}

__global__ void __launch_bounds__(448, 1) rnn_kernel(
    const float* __restrict__ x,     // [T, B, 2]
    const float* __restrict__ Wih,   // [H, 2]
    const float* __restrict__ Whh,   // [H, H]
    const float* __restrict__ bih,   // [H]
    const float* __restrict__ bhh,   // [H]
    const float* __restrict__ Wout,  // [1, H]
    const float* __restrict__ bOut,  // [1]
    float* __restrict__ out)         // [T, B, 1]
{
    __shared__ __align__(16) float2 xsm[TT];        // input sequence, 16 KB
    __shared__ __align__(16) float  hsm[2][HP];     // double-buffered h (+pads)
    __shared__ __align__(16) float  houtsm[2][4 * JT]; // h quads, parity buffers

    const int tid  = threadIdx.x;
    const int b    = blockIdx.x;
    const int lane = tid & 31;
    const int kc   = tid & 7;        // k-chunk
    const int jt   = tid >> 3;       // j-quad
    const bool compute = (tid < 416);
    const bool red0    = compute && (kc == 0);

    // Preload input sequence for this batch
    for (int i = tid; i < TT; i += 448)
        xsm[i] = *(const float2*)(x + ((size_t)i * BB + b) * 2);

    // W registers: 4 rows (j = 4jt..4jt+3) x chunk [28kc, 28kc+28) as 14 u64 each.
    // Pad rows (j>=200) and pad cols (k>=200) are zero, EXCEPT kc==7 carries the
    // xproj/bias fold: pair12 = (Wih[j,0], Wih[j,1])  [k=220,221 -> (x0,x1)]
    //                  pair13 = (bias_j, 0)           [k=222,223 -> (1, 0)]
    ull wr[4][14];
    if (compute) {
#pragma unroll
        for (int r = 0; r < 4; r++) {
            const int j = 4 * jt + r;
            const bool vj = (j < HH);
            const float* wrow = Whh + (size_t)j * HH + KC * kc;
            if (kc < 7) {
#pragma unroll
                for (int i = 0; i < 14; i++)
                    wr[r][i] = vj ? *(const ull*)(wrow + 2 * i) : 0ull;
            } else {
                // k = 196..223: pairs 0,1 real (k 196..199); 2..11 zero; 12,13 fold
                wr[r][0] = vj ? *(const ull*)(wrow)     : 0ull;
                wr[r][1] = vj ? *(const ull*)(wrow + 2) : 0ull;
#pragma unroll
                for (int i = 2; i < 12; i++) wr[r][i] = 0ull;
                wr[r][12] = vj ? pack2(Wih[2 * j], Wih[2 * j + 1]) : 0ull;
                wr[r][13] = vj ? pack2(bih[j] + bhh[j], 0.0f)      : 0ull;
            }
        }
    }

    // Out-warp constants: Wout slices + bias
    float wo[7];
    if (!compute) {
#pragma unroll
        for (int i = 0; i < 7; i++) {
            int idx = lane + 32 * i;
            wo[i] = (idx < HH) ? Wout[idx] : 0.0f;
        }
    }
    const float bo = bOut[0];

    // Init: h_0 = 0, pads = 0; then constant/x pad slots in both buffers
    for (int i = tid; i < 2 * HP; i += 448) ((float*)hsm)[i] = 0.0f;
    __syncthreads();
    if (tid == 0) {
        float2 x0 = xsm[0];
        hsm[0][220] = x0.x;
        hsm[0][221] = x0.y;
        hsm[0][222] = 1.0f;
        hsm[1][222] = 1.0f;
    }
    __syncthreads();

    auto step = [&](int t, int rp) {
        if (compute) {
            // 7 LDS.128 over this chunk, reused across 4 W rows (j-tiling)
            const ulonglong2* hp = (const ulonglong2*)(&hsm[rp][KC * kc]);
            ull acc[4] = {0ull, 0ull, 0ull, 0ull};
#pragma unroll
            for (int i = 0; i < 7; i++) {
                ulonglong2 hv = hp[i];
#pragma unroll
                for (int r = 0; r < 4; r++) {
                    fma2(acc[r], hv.x, wr[r][2 * i]);
                    fma2(acc[r], hv.y, wr[r][2 * i + 1]);
                }
            }
            float p[4];
#pragma unroll
            for (int r = 0; r < 4; r++) {
                float lo, hi;
                unpack2(acc[r], lo, hi);
                p[r] = lo + hi;
            }
            // reduce across the 8 k-chunk lanes (consecutive lanes, xor 1,2,4)
#pragma unroll
            for (int r = 0; r < 4; r++) {
                p[r] += __shfl_xor_sync(0xFFFFFFFFu, p[r], 1);
                p[r] += __shfl_xor_sync(0xFFFFFFFFu, p[r], 2);
                p[r] += __shfl_xor_sync(0xFFFFFFFFu, p[r], 4);
            }
            if (red0 && jt < 50) {   // writer for real j quads (j < 200)
                float4 hq;
                hq.x = tanh_hw(p[0]);
                hq.y = tanh_hw(p[1]);
                hq.z = tanh_hw(p[2]);
                hq.w = tanh_hw(p[3]);
                *(float4*)(&hsm[rp ^ 1][4 * jt]) = hq;
                *(float4*)(&houtsm[t & 1][4 * jt]) = hq;
            }
        } else {
            if (lane == 0 && t + 1 < TT) {    // stage x_{t+1} into next buffer
                float2 xn = xsm[t + 1];
                hsm[rp ^ 1][220] = xn.x;
                hsm[rp ^ 1][221] = xn.y;
            }
            if (t > 0) {                       // head for step t-1 (overlapped)
                const float* hv = houtsm[(t - 1) & 1];
                float acc = 0.0f;
#pragma unroll
                for (int i = 0; i < 7; i++) {
                    int idx = lane + 32 * i;
                    if (idx < HH) acc = fmaf(hv[idx], wo[i], acc);
                }
#pragma unroll
                for (int off = 16; off; off >>= 1)
                    acc += __shfl_xor_sync(0xFFFFFFFFu, acc, off);
                if (lane == 0) out[(size_t)(t - 1) * BB + b] = acc + bo;
            }
        }
        __syncthreads();
    };

#pragma unroll 1
    for (int t = 0; t < TT; t += 2) {
        step(t, 0);
        step(t + 1, 1);
    }

    // Final step's head output (t = TT-1, parity 1)
    if (!compute) {
        const float* hv = houtsm[1];
        float acc = 0.0f;
#pragma unroll
        for (int i = 0; i < 7; i++) {
            int idx = lane + 32 * i;
            if (idx < HH) acc = fmaf(hv[idx], wo[i], acc);
        }
#pragma unroll
        for (int off = 16; off; off >>= 1)
            acc += __shfl_xor_sync(0xFFFFFFFFu, acc, off);
        if (lane == 0) out[(size_t)(TT - 1) * BB + b] = acc + bo;
    }
}

extern "C" void kernel_launch(void* const* d_in, const int* in_sizes, int n_in,
                              void* d_out, int out_size) {
    const float* input_seq = (const float*)d_in[0];  // [T,B,2]
    const float* W_ih      = (const float*)d_in[1];  // [H,2]
    const float* W_hh      = (const float*)d_in[2];  // [H,H]
    const float* b_ih      = (const float*)d_in[3];  // [H]
    const float* b_hh      = (const float*)d_in[4];  // [H]
    const float* W_out     = (const float*)d_in[5];  // [1,H]
    const float* b_out     = (const float*)d_in[6];  // [1]
    float* out = (float*)d_out;                      // [T,B,1]

    rnn_kernel<<<BB, 448>>>(input_seq, W_ih, W_hh, b_ih, b_hh, W_out, b_out, out);
}